// round 1
// baseline (speedup 1.0000x reference)
#include <cuda_runtime.h>
#include <cstdint>

// ---------------- problem constants (fixed by reference_code) ----------------
#define N_USERS 100000
#define N_ITEMS 50000
#define N_NODES 150000          // N_USERS + N_ITEMS
#define KPU 32                  // items per user
#define E_UI  (N_USERS * KPU)   // 3,200,000 user->item edges (first block)
#define SELF_BASE (2 * E_UI)    // self-loop edges start at 6,400,000
#define D 64                    // embed dim (all layers)
#define OD 256                  // output row width: 64 + 3*64

// ---------------- device scratch (no allocation allowed) ----------------
__device__ float g_side[(size_t)N_NODES * D];   // 38.4 MB SpMM output
__device__ int   g_cnt [N_ITEMS];
__device__ int   g_fill[N_ITEMS];
__device__ int   g_off [N_ITEMS + 1];
__device__ int   g_adj [E_UI];                  // 12.8 MB item->user lists

// ---------------- 1) ego copy: out[:,0:64] = concat(user_embed, item_embed) -
__global__ void ego_copy_kernel(const float* __restrict__ ue,
                                const float* __restrict__ ie,
                                float* __restrict__ out) {
    int idx = blockIdx.x * blockDim.x + threadIdx.x;   // one float4 each
    if (idx >= N_NODES * (D / 4)) return;
    int n  = idx >> 4;          // node
    int c4 = idx & 15;          // float4 index within 64 floats
    float4 v = (n < N_USERS)
        ? reinterpret_cast<const float4*>(ue)[(size_t)n * (D/4) + c4]
        : reinterpret_cast<const float4*>(ie)[(size_t)(n - N_USERS) * (D/4) + c4];
    reinterpret_cast<float4*>(out)[(size_t)n * (OD/4) + c4] = v;
}

// ---------------- 2) item-CSR build ----------------
__global__ void zero_counts_kernel() {
    int i = blockIdx.x * blockDim.x + threadIdx.x;
    if (i < N_ITEMS) { g_cnt[i] = 0; g_fill[i] = 0; }
}

__global__ void hist_kernel(const int* __restrict__ cols) {
    int e = blockIdx.x * blockDim.x + threadIdx.x;
    if (e < E_UI) atomicAdd(&g_cnt[cols[e] - N_USERS], 1);
}

__global__ void scan_kernel() {
    __shared__ int part[1024];
    const int CH = (N_ITEMS + 1023) / 1024;   // 49
    int t = threadIdx.x;
    int base = t * CH;
    int s = 0;
    for (int i = 0; i < CH; i++) {
        int idx = base + i;
        if (idx < N_ITEMS) s += g_cnt[idx];
    }
    part[t] = s;
    __syncthreads();
    for (int ofs = 1; ofs < 1024; ofs <<= 1) {
        int v = (t >= ofs) ? part[t - ofs] : 0;
        __syncthreads();
        part[t] += v;
        __syncthreads();
    }
    int run = (t == 0) ? 0 : part[t - 1];
    for (int i = 0; i < CH; i++) {
        int idx = base + i;
        if (idx < N_ITEMS) { g_off[idx] = run; run += g_cnt[idx]; }
    }
    if (t == 0) g_off[N_ITEMS] = part[1023];
}

__global__ void fill_kernel(const int* __restrict__ cols) {
    int e = blockIdx.x * blockDim.x + threadIdx.x;
    if (e >= E_UI) return;
    int item = cols[e] - N_USERS;
    int pos  = g_off[item] + atomicAdd(&g_fill[item], 1);
    g_adj[pos] = e >> 5;        // user id = edge/32 (user-major layout)
}

// ---------------- 3) SpMM, user side (gather-only) ----------------
// side[u] = vals_self[u] * ( sum_{j<32} prev[cols[32u+j]] + prev[u] )
__global__ void spmm_user_kernel(const int* __restrict__ cols,
                                 const float* __restrict__ vals,
                                 const float* __restrict__ prev,   // stride OD
                                 float* __restrict__ side) {
    int warp = (blockIdx.x * blockDim.x + threadIdx.x) >> 5;
    if (warp >= N_USERS) return;
    int lane = threadIdx.x & 31;
    int u = warp;

    int myc = cols[u * KPU + lane];   // one coalesced load, shuffled below

    const float2* prow = reinterpret_cast<const float2*>(prev + (size_t)u * OD);
    float2 acc = prow[lane];          // self loop
    #pragma unroll
    for (int j = 0; j < KPU; j++) {
        int c = __shfl_sync(0xffffffffu, myc, j);
        float2 v = reinterpret_cast<const float2*>(prev + (size_t)c * OD)[lane];
        acc.x += v.x; acc.y += v.y;
    }
    float sv = vals[SELF_BASE + u];   // 1/deg[u]
    reinterpret_cast<float2*>(side + (size_t)u * D)[lane] =
        make_float2(acc.x * sv, acc.y * sv);
}

// ---------------- 4) SpMM, item side (gather via CSR) ----------------
__global__ void spmm_item_kernel(const float* __restrict__ vals,
                                 const float* __restrict__ prev,   // stride OD
                                 float* __restrict__ side) {
    int warp = (blockIdx.x * blockDim.x + threadIdx.x) >> 5;
    if (warp >= N_ITEMS) return;
    int lane = threadIdx.x & 31;
    int node = N_USERS + warp;
    int beg = g_off[warp], end = g_off[warp + 1];

    float2 acc = reinterpret_cast<const float2*>(prev + (size_t)node * OD)[lane];
    for (int p = beg; p < end; p += 32) {
        int rem = end - p;
        int myu = (lane < rem) ? g_adj[p + lane] : 0;
        if (rem >= 32) {
            #pragma unroll
            for (int j = 0; j < 32; j++) {
                int uu = __shfl_sync(0xffffffffu, myu, j);
                float2 v = reinterpret_cast<const float2*>(prev + (size_t)uu * OD)[lane];
                acc.x += v.x; acc.y += v.y;
            }
        } else {
            for (int j = 0; j < rem; j++) {
                int uu = __shfl_sync(0xffffffffu, myu, j);
                float2 v = reinterpret_cast<const float2*>(prev + (size_t)uu * OD)[lane];
                acc.x += v.x; acc.y += v.y;
            }
        }
    }
    float sv = vals[SELF_BASE + node];   // 1/deg[item]
    reinterpret_cast<float2*>(side + (size_t)node * D)[lane] =
        make_float2(acc.x * sv, acc.y * sv);
}

// ---------------- 5) dense: msg = lrelu(side@Ws+bs + (side*prev)@Wp+bp); L2-normalize
// 4 threads per row (16 cols each), 64 rows per 256-thread block, weights in SMEM.
__global__ void __launch_bounds__(256)
dense_layer_kernel(const float* __restrict__ side,     // [N, 64] packed
                   const float* __restrict__ prevc,    // stride OD (out col 64k)
                   float* __restrict__ outc,           // stride OD (out col 64(k+1))
                   const float* __restrict__ Ws, const float* __restrict__ bs,
                   const float* __restrict__ Wp, const float* __restrict__ bp) {
    __shared__ float sWs[D * D];
    __shared__ float sWp[D * D];
    __shared__ float sb[D];
    int tx = threadIdx.x;
    for (int i = tx; i < D * D; i += 256) { sWs[i] = Ws[i]; sWp[i] = Wp[i]; }
    if (tx < D) sb[tx] = bs[tx] + bp[tx];
    __syncthreads();

    int cg  = tx & 3;           // column group: 16 cols
    int r   = tx >> 2;          // row slot 0..63
    int row = blockIdx.x * 64 + r;
    if (row >= N_NODES) return; // whole-warp uniform at the tail

    const float4* srow = reinterpret_cast<const float4*>(side  + (size_t)row * D);
    const float4* prow = reinterpret_cast<const float4*>(prevc + (size_t)row * OD);

    float acc[16];
    #pragma unroll
    for (int c = 0; c < 16; c++) acc[c] = sb[cg * 16 + c];

    #pragma unroll
    for (int j4 = 0; j4 < 16; j4++) {
        float4 s4 = srow[j4];
        float4 p4 = prow[j4];
        float ss4[4] = {s4.x, s4.y, s4.z, s4.w};
        float pp4[4] = {p4.x, p4.y, p4.z, p4.w};
        #pragma unroll
        for (int jj = 0; jj < 4; jj++) {
            int j = j4 * 4 + jj;
            float s  = ss4[jj];
            float sp = s * pp4[jj];
            const float4* wsr = reinterpret_cast<const float4*>(sWs + j * D + cg * 16);
            const float4* wpr = reinterpret_cast<const float4*>(sWp + j * D + cg * 16);
            #pragma unroll
            for (int q = 0; q < 4; q++) {
                float4 w1 = wsr[q], w2 = wpr[q];
                acc[q*4+0] += s * w1.x + sp * w2.x;
                acc[q*4+1] += s * w1.y + sp * w2.y;
                acc[q*4+2] += s * w1.z + sp * w2.z;
                acc[q*4+3] += s * w1.w + sp * w2.w;
            }
        }
    }

    // leaky relu + rowwise L2 norm (4 threads share a row)
    float sq = 0.0f;
    #pragma unroll
    for (int c = 0; c < 16; c++) {
        float v = acc[c];
        v = (v >= 0.0f) ? v : 0.2f * v;
        acc[c] = v;
        sq += v * v;
    }
    sq += __shfl_xor_sync(0xffffffffu, sq, 1);
    sq += __shfl_xor_sync(0xffffffffu, sq, 2);
    float inv = 1.0f / fmaxf(sqrtf(sq), 1e-12f);

    float* dst = outc + (size_t)row * OD + cg * 16;
    #pragma unroll
    for (int q = 0; q < 4; q++) {
        float4 o;
        o.x = acc[q*4+0] * inv; o.y = acc[q*4+1] * inv;
        o.z = acc[q*4+2] * inv; o.w = acc[q*4+3] * inv;
        reinterpret_cast<float4*>(dst)[q] = o;
    }
}

// ---------------- launch ----------------
extern "C" void kernel_launch(void* const* d_in, const int* in_sizes, int n_in,
                              void* d_out, int out_size) {
    (void)in_sizes; (void)n_in; (void)out_size;
    const int*   cols = (const int*)d_in[1];
    const float* vals = (const float*)d_in[2];
    const float* ue   = (const float*)d_in[3];
    const float* ie   = (const float*)d_in[4];
    float* out = (float*)d_out;

    // ego embeddings -> out columns [0,64)
    {
        int tot = N_NODES * (D / 4);
        ego_copy_kernel<<<(tot + 255) / 256, 256>>>(ue, ie, out);
    }

    // build item CSR (per-launch, deterministic work)
    zero_counts_kernel<<<(N_ITEMS + 255) / 256, 256>>>();
    hist_kernel<<<(E_UI + 255) / 256, 256>>>(cols);
    scan_kernel<<<1, 1024>>>();
    fill_kernel<<<(E_UI + 255) / 256, 256>>>(cols);

    // 3 NGCF layers, each writing out columns [64(k+1), 64(k+2))
    for (int k = 0; k < 3; k++) {
        const float* prevc = out + (size_t)64 * k;        // stride OD
        float*       outc  = out + (size_t)64 * (k + 1);  // stride OD
        const float* Ws = (const float*)d_in[5 + 4 * k + 0];
        const float* bs = (const float*)d_in[5 + 4 * k + 1];
        const float* Wp = (const float*)d_in[5 + 4 * k + 2];
        const float* bp = (const float*)d_in[5 + 4 * k + 3];

        spmm_user_kernel<<<(N_USERS * 32 + 255) / 256, 256>>>(cols, vals, prevc, g_side);
        spmm_item_kernel<<<(N_ITEMS * 32 + 255) / 256, 256>>>(vals, prevc, g_side);
        dense_layer_kernel<<<(N_NODES + 63) / 64, 256>>>(g_side, prevc, outc, Ws, bs, Wp, bp);
    }
}

// round 2
// speedup vs baseline: 1.0390x; 1.0390x over previous
#include <cuda_runtime.h>
#include <cstdint>

// ---------------- problem constants (fixed by reference_code) ----------------
#define N_USERS 100000
#define N_ITEMS 50000
#define N_NODES 150000          // N_USERS + N_ITEMS
#define KPU 32                  // items per user
#define E_UI  (N_USERS * KPU)   // 3,200,000 user->item edges (first block)
#define SELF_BASE (2 * E_UI)    // self-loop edges start at 6,400,000
#define D 64                    // embed dim (all layers)
#define OD 256                  // output row width: 64 + 3*64

// ---------------- device scratch (no allocation allowed) ----------------
__device__ float g_side[(size_t)N_NODES * D];   // 38.4 MB SpMM output
__device__ int   g_cnt [N_ITEMS];
__device__ int   g_fill[N_ITEMS];
__device__ int   g_off [N_ITEMS];
__device__ int   g_adj [E_UI];                  // 12.8 MB item->user lists
__device__ int   g_total;

// ---------------- 1) ego copy: out[:,0:64] = concat(user_embed, item_embed) -
__global__ void ego_copy_kernel(const float* __restrict__ ue,
                                const float* __restrict__ ie,
                                float* __restrict__ out) {
    int idx = blockIdx.x * blockDim.x + threadIdx.x;   // one float4 each
    if (idx >= N_NODES * (D / 4)) return;
    int n  = idx >> 4;          // node
    int c4 = idx & 15;          // float4 index within 64 floats
    float4 v = (n < N_USERS)
        ? reinterpret_cast<const float4*>(ue)[(size_t)n * (D/4) + c4]
        : reinterpret_cast<const float4*>(ie)[(size_t)(n - N_USERS) * (D/4) + c4];
    reinterpret_cast<float4*>(out)[(size_t)n * (OD/4) + c4] = v;
}

// ---------------- 2) item-CSR build ----------------
__global__ void zero_counts_kernel() {
    int i = blockIdx.x * blockDim.x + threadIdx.x;
    if (i < N_ITEMS) { g_cnt[i] = 0; g_fill[i] = 0; }
    if (i == 0) g_total = 0;
}

__global__ void hist_kernel(const int* __restrict__ cols) {
    int e = blockIdx.x * blockDim.x + threadIdx.x;
    if (e < E_UI) atomicAdd(&g_cnt[cols[e] - N_USERS], 1);
}

// Per-block inclusive scan + atomic base reservation. CSR segment order across
// blocks is arbitrary (doesn't matter — only disjoint contiguous ranges needed).
__global__ void offsets_kernel() {
    __shared__ int sdata[256];
    __shared__ int sbase;
    int tx = threadIdx.x;
    int i  = blockIdx.x * 256 + tx;
    int v  = (i < N_ITEMS) ? g_cnt[i] : 0;
    sdata[tx] = v;
    __syncthreads();
    #pragma unroll
    for (int ofs = 1; ofs < 256; ofs <<= 1) {
        int t = (tx >= ofs) ? sdata[tx - ofs] : 0;
        __syncthreads();
        sdata[tx] += t;
        __syncthreads();
    }
    if (tx == 255) sbase = atomicAdd(&g_total, sdata[255]);
    __syncthreads();
    if (i < N_ITEMS) g_off[i] = sbase + sdata[tx] - v;
}

__global__ void fill_kernel(const int* __restrict__ cols) {
    int e = blockIdx.x * blockDim.x + threadIdx.x;
    if (e >= E_UI) return;
    int item = cols[e] - N_USERS;
    int pos  = g_off[item] + atomicAdd(&g_fill[item], 1);
    g_adj[pos] = e >> 5;        // user id = edge/32 (user-major layout)
}

// ---------------- 3) SpMM, user side (gather-only, half-warp per user) -------
// side[u] = vals_self[u] * ( sum_{j<32} prev[cols[32u+j]] + prev[u] )
// 16 lanes x float4 = one 256B row per round; 2 users per warp.
__global__ void spmm_user_kernel(const int* __restrict__ cols,
                                 const float* __restrict__ vals,
                                 const float* __restrict__ prev,   // stride OD
                                 float* __restrict__ side) {
    int hw = (blockIdx.x * blockDim.x + threadIdx.x) >> 4;
    if (hw >= N_USERS) return;
    int hl = threadIdx.x & 15;
    unsigned hmask = 0xFFFFu << (threadIdx.x & 16);
    int u = hw;

    const int* cu = cols + u * KPU;
    int c_lo = cu[hl];
    int c_hi = cu[16 + hl];

    float4 acc = reinterpret_cast<const float4*>(prev + (size_t)u * OD)[hl]; // self
    #pragma unroll
    for (int j = 0; j < 16; j++) {
        int c = __shfl_sync(hmask, c_lo, j, 16);
        float4 v = reinterpret_cast<const float4*>(prev + (size_t)c * OD)[hl];
        acc.x += v.x; acc.y += v.y; acc.z += v.z; acc.w += v.w;
    }
    #pragma unroll
    for (int j = 0; j < 16; j++) {
        int c = __shfl_sync(hmask, c_hi, j, 16);
        float4 v = reinterpret_cast<const float4*>(prev + (size_t)c * OD)[hl];
        acc.x += v.x; acc.y += v.y; acc.z += v.z; acc.w += v.w;
    }
    float sv = vals[SELF_BASE + u];   // 1/deg[u]
    float4 o = make_float4(acc.x * sv, acc.y * sv, acc.z * sv, acc.w * sv);
    reinterpret_cast<float4*>(side + (size_t)u * D)[hl] = o;
}

// ---------------- 4) SpMM, item side (gather via CSR, half-warp per item) ----
__global__ void spmm_item_kernel(const float* __restrict__ vals,
                                 const float* __restrict__ prev,   // stride OD
                                 float* __restrict__ side) {
    int hw = (blockIdx.x * blockDim.x + threadIdx.x) >> 4;
    if (hw >= N_ITEMS) return;
    int hl = threadIdx.x & 15;
    unsigned hmask = 0xFFFFu << (threadIdx.x & 16);
    int node = N_USERS + hw;
    int beg = g_off[hw];
    int cnt = g_cnt[hw];

    float4 acc = reinterpret_cast<const float4*>(prev + (size_t)node * OD)[hl]; // self

    int p = 0;
    for (; p + 16 <= cnt; p += 16) {
        int myu = g_adj[beg + p + hl];
        #pragma unroll
        for (int j = 0; j < 16; j++) {
            int uu = __shfl_sync(hmask, myu, j, 16);
            float4 v = reinterpret_cast<const float4*>(prev + (size_t)uu * OD)[hl];
            acc.x += v.x; acc.y += v.y; acc.z += v.z; acc.w += v.w;
        }
    }
    int rem = cnt - p;
    if (rem > 0) {
        int myu = (hl < rem) ? g_adj[beg + p + hl] : 0;
        for (int j = 0; j < rem; j++) {
            int uu = __shfl_sync(hmask, myu, j, 16);
            float4 v = reinterpret_cast<const float4*>(prev + (size_t)uu * OD)[hl];
            acc.x += v.x; acc.y += v.y; acc.z += v.z; acc.w += v.w;
        }
    }
    float sv = vals[SELF_BASE + node];   // 1/deg[item]
    float4 o = make_float4(acc.x * sv, acc.y * sv, acc.z * sv, acc.w * sv);
    reinterpret_cast<float4*>(side + (size_t)node * D)[hl] = o;
}

// ---------------- 5) dense: msg = lrelu(side@Ws+bs + (side*prev)@Wp+bp); L2-normalize
// 4 threads per row (16 cols each), 64 rows per 256-thread block, weights in SMEM.
__global__ void __launch_bounds__(256)
dense_layer_kernel(const float* __restrict__ side,     // [N, 64] packed
                   const float* __restrict__ prevc,    // stride OD (out col 64k)
                   float* __restrict__ outc,           // stride OD (out col 64(k+1))
                   const float* __restrict__ Ws, const float* __restrict__ bs,
                   const float* __restrict__ Wp, const float* __restrict__ bp) {
    __shared__ float sWs[D * D];
    __shared__ float sWp[D * D];
    __shared__ float sb[D];
    int tx = threadIdx.x;
    for (int i = tx; i < D * D; i += 256) { sWs[i] = Ws[i]; sWp[i] = Wp[i]; }
    if (tx < D) sb[tx] = bs[tx] + bp[tx];
    __syncthreads();

    int cg  = tx & 3;           // column group: 16 cols
    int r   = tx >> 2;          // row slot 0..63
    int row = blockIdx.x * 64 + r;
    if (row >= N_NODES) return; // whole-warp uniform at the tail

    const float4* srow = reinterpret_cast<const float4*>(side  + (size_t)row * D);
    const float4* prow = reinterpret_cast<const float4*>(prevc + (size_t)row * OD);

    float acc[16];
    #pragma unroll
    for (int c = 0; c < 16; c++) acc[c] = sb[cg * 16 + c];

    #pragma unroll
    for (int j4 = 0; j4 < 16; j4++) {
        float4 s4 = srow[j4];
        float4 p4 = prow[j4];
        float ss4[4] = {s4.x, s4.y, s4.z, s4.w};
        float pp4[4] = {p4.x, p4.y, p4.z, p4.w};
        #pragma unroll
        for (int jj = 0; jj < 4; jj++) {
            int j = j4 * 4 + jj;
            float s  = ss4[jj];
            float sp = s * pp4[jj];
            const float4* wsr = reinterpret_cast<const float4*>(sWs + j * D + cg * 16);
            const float4* wpr = reinterpret_cast<const float4*>(sWp + j * D + cg * 16);
            #pragma unroll
            for (int q = 0; q < 4; q++) {
                float4 w1 = wsr[q], w2 = wpr[q];
                acc[q*4+0] += s * w1.x + sp * w2.x;
                acc[q*4+1] += s * w1.y + sp * w2.y;
                acc[q*4+2] += s * w1.z + sp * w2.z;
                acc[q*4+3] += s * w1.w + sp * w2.w;
            }
        }
    }

    // leaky relu + rowwise L2 norm (4 threads share a row)
    float sq = 0.0f;
    #pragma unroll
    for (int c = 0; c < 16; c++) {
        float v = acc[c];
        v = (v >= 0.0f) ? v : 0.2f * v;
        acc[c] = v;
        sq += v * v;
    }
    sq += __shfl_xor_sync(0xffffffffu, sq, 1);
    sq += __shfl_xor_sync(0xffffffffu, sq, 2);
    float inv = 1.0f / fmaxf(sqrtf(sq), 1e-12f);

    float* dst = outc + (size_t)row * OD + cg * 16;
    #pragma unroll
    for (int q = 0; q < 4; q++) {
        float4 o;
        o.x = acc[q*4+0] * inv; o.y = acc[q*4+1] * inv;
        o.z = acc[q*4+2] * inv; o.w = acc[q*4+3] * inv;
        reinterpret_cast<float4*>(dst)[q] = o;
    }
}

// ---------------- launch ----------------
extern "C" void kernel_launch(void* const* d_in, const int* in_sizes, int n_in,
                              void* d_out, int out_size) {
    (void)in_sizes; (void)n_in; (void)out_size;
    const int*   cols = (const int*)d_in[1];
    const float* vals = (const float*)d_in[2];
    const float* ue   = (const float*)d_in[3];
    const float* ie   = (const float*)d_in[4];
    float* out = (float*)d_out;

    // ego embeddings -> out columns [0,64)
    {
        int tot = N_NODES * (D / 4);
        ego_copy_kernel<<<(tot + 255) / 256, 256>>>(ue, ie, out);
    }

    // build item CSR (per-launch, deterministic work)
    zero_counts_kernel<<<(N_ITEMS + 255) / 256, 256>>>();
    hist_kernel<<<(E_UI + 255) / 256, 256>>>(cols);
    offsets_kernel<<<(N_ITEMS + 255) / 256, 256>>>();
    fill_kernel<<<(E_UI + 255) / 256, 256>>>(cols);

    // 3 NGCF layers, each writing out columns [64(k+1), 64(k+2))
    for (int k = 0; k < 3; k++) {
        const float* prevc = out + (size_t)64 * k;        // stride OD
        float*       outc  = out + (size_t)64 * (k + 1);  // stride OD
        const float* Ws = (const float*)d_in[5 + 4 * k + 0];
        const float* bs = (const float*)d_in[5 + 4 * k + 1];
        const float* Wp = (const float*)d_in[5 + 4 * k + 2];
        const float* bp = (const float*)d_in[5 + 4 * k + 3];

        spmm_user_kernel<<<(N_USERS * 16 + 255) / 256, 256>>>(cols, vals, prevc, g_side);
        spmm_item_kernel<<<(N_ITEMS * 16 + 255) / 256, 256>>>(vals, prevc, g_side);
        dense_layer_kernel<<<(N_NODES + 63) / 64, 256>>>(g_side, prevc, outc, Ws, bs, Wp, bp);
    }
}

// round 3
// speedup vs baseline: 1.1348x; 1.0922x over previous
#include <cuda_runtime.h>
#include <cstdint>

// ---------------- problem constants (fixed by reference_code) ----------------
#define N_USERS 100000
#define N_ITEMS 50000
#define N_NODES 150000          // N_USERS + N_ITEMS
#define KPU 32                  // items per user
#define E_UI  (N_USERS * KPU)   // 3,200,000 user->item edges (first block)
#define SELF_BASE (2 * E_UI)    // self-loop edges start at 6,400,000
#define D 64                    // embed dim (all layers)
#define OD 256                  // output row width: 64 + 3*64

// ---------------- device scratch (no allocation allowed) ----------------
__device__ float g_side[(size_t)N_NODES * D];   // 38.4 MB SpMM output
__device__ int   g_cnt [N_ITEMS];
__device__ int   g_fill[N_ITEMS];
__device__ int   g_off [N_ITEMS];
__device__ int   g_adj [E_UI];                  // 12.8 MB item->user lists
__device__ int   g_total;

// ---------------- 1) ego copy: out[:,0:64] = concat(user_embed, item_embed) -
__global__ void ego_copy_kernel(const float* __restrict__ ue,
                                const float* __restrict__ ie,
                                float* __restrict__ out) {
    int idx = blockIdx.x * blockDim.x + threadIdx.x;   // one float4 each
    if (idx >= N_NODES * (D / 4)) return;
    int n  = idx >> 4;          // node
    int c4 = idx & 15;          // float4 index within 64 floats
    float4 v = (n < N_USERS)
        ? reinterpret_cast<const float4*>(ue)[(size_t)n * (D/4) + c4]
        : reinterpret_cast<const float4*>(ie)[(size_t)(n - N_USERS) * (D/4) + c4];
    reinterpret_cast<float4*>(out)[(size_t)n * (OD/4) + c4] = v;
}

// ---------------- 2) item-CSR build ----------------
__global__ void zero_counts_kernel() {
    int i = blockIdx.x * blockDim.x + threadIdx.x;
    if (i < N_ITEMS) { g_cnt[i] = 0; g_fill[i] = 0; }
    if (i == 0) g_total = 0;
}

__global__ void hist_kernel(const int* __restrict__ cols) {
    int e = blockIdx.x * blockDim.x + threadIdx.x;
    if (e < E_UI) atomicAdd(&g_cnt[cols[e] - N_USERS], 1);
}

// Per-block inclusive scan + atomic base reservation (segment order arbitrary).
__global__ void offsets_kernel() {
    __shared__ int sdata[256];
    __shared__ int sbase;
    int tx = threadIdx.x;
    int i  = blockIdx.x * 256 + tx;
    int v  = (i < N_ITEMS) ? g_cnt[i] : 0;
    sdata[tx] = v;
    __syncthreads();
    #pragma unroll
    for (int ofs = 1; ofs < 256; ofs <<= 1) {
        int t = (tx >= ofs) ? sdata[tx - ofs] : 0;
        __syncthreads();
        sdata[tx] += t;
        __syncthreads();
    }
    if (tx == 255) sbase = atomicAdd(&g_total, sdata[255]);
    __syncthreads();
    if (i < N_ITEMS) g_off[i] = sbase + sdata[tx] - v;
}

__global__ void fill_kernel(const int* __restrict__ cols) {
    int e = blockIdx.x * blockDim.x + threadIdx.x;
    if (e >= E_UI) return;
    int item = cols[e] - N_USERS;
    int pos  = g_off[item] + atomicAdd(&g_fill[item], 1);
    g_adj[pos] = e >> 5;        // user id = edge/32 (user-major layout)
}

// ---------------- 3) fused SpMM over ALL nodes (half-warp per node) ----------
// side[n] = (1/deg[n]) * ( sum_{c in N(n)} prev[c] + prev[n] )
__global__ void spmm_all_kernel(const int* __restrict__ cols,
                                const float* __restrict__ vals,
                                const float* __restrict__ prev,   // stride OD
                                float* __restrict__ side) {
    int hw = (blockIdx.x * blockDim.x + threadIdx.x) >> 4;
    if (hw >= N_NODES) return;
    int hl = threadIdx.x & 15;
    unsigned hmask = 0xFFFFu << (threadIdx.x & 16);

    float4 acc = reinterpret_cast<const float4*>(prev + (size_t)hw * OD)[hl]; // self

    if (hw < N_USERS) {
        const int* cu = cols + hw * KPU;
        int c_lo = cu[hl];
        int c_hi = cu[16 + hl];
        #pragma unroll
        for (int j = 0; j < 16; j++) {
            int c = __shfl_sync(hmask, c_lo, j, 16);
            float4 v = reinterpret_cast<const float4*>(prev + (size_t)c * OD)[hl];
            acc.x += v.x; acc.y += v.y; acc.z += v.z; acc.w += v.w;
        }
        #pragma unroll
        for (int j = 0; j < 16; j++) {
            int c = __shfl_sync(hmask, c_hi, j, 16);
            float4 v = reinterpret_cast<const float4*>(prev + (size_t)c * OD)[hl];
            acc.x += v.x; acc.y += v.y; acc.z += v.z; acc.w += v.w;
        }
    } else {
        int it = hw - N_USERS;
        int beg = g_off[it];
        int cnt = g_cnt[it];
        int p = 0;
        for (; p + 16 <= cnt; p += 16) {
            int myu = g_adj[beg + p + hl];
            #pragma unroll
            for (int j = 0; j < 16; j++) {
                int uu = __shfl_sync(hmask, myu, j, 16);
                float4 v = reinterpret_cast<const float4*>(prev + (size_t)uu * OD)[hl];
                acc.x += v.x; acc.y += v.y; acc.z += v.z; acc.w += v.w;
            }
        }
        int rem = cnt - p;
        if (rem > 0) {
            int myu = (hl < rem) ? g_adj[beg + p + hl] : 0;
            for (int j = 0; j < rem; j++) {
                int uu = __shfl_sync(hmask, myu, j, 16);
                float4 v = reinterpret_cast<const float4*>(prev + (size_t)uu * OD)[hl];
                acc.x += v.x; acc.y += v.y; acc.z += v.z; acc.w += v.w;
            }
        }
    }
    float sv = vals[SELF_BASE + hw];   // 1/deg[node]
    float4 o = make_float4(acc.x * sv, acc.y * sv, acc.z * sv, acc.w * sv);
    reinterpret_cast<float4*>(side + (size_t)hw * D)[hl] = o;
}

// ---------------- 4) dense: msg = lrelu(side@Ws+bs + (side*prev)@Wp+bp); L2-norm
// 4 threads per row-column-slice, FOUR rows per thread to amortize weight LDS.
// Block = 256 threads covers 256 rows.
__global__ void __launch_bounds__(256, 1)
dense_layer_kernel(const float* __restrict__ side,     // [N, 64] packed
                   const float* __restrict__ prevc,    // stride OD
                   float* __restrict__ outc,           // stride OD
                   const float* __restrict__ Ws, const float* __restrict__ bs,
                   const float* __restrict__ Wp, const float* __restrict__ bp) {
    __shared__ float sWs[D * D];
    __shared__ float sWp[D * D];
    __shared__ float sb[D];
    int tx = threadIdx.x;
    for (int i = tx; i < D * D; i += 256) { sWs[i] = Ws[i]; sWp[i] = Wp[i]; }
    if (tx < D) sb[tx] = bs[tx] + bp[tx];
    __syncthreads();

    int cg = tx & 3;            // column group: 16 cols
    int rs = tx >> 2;           // row slot 0..63
    int base = blockIdx.x * 256;

    int   rows[4];
    bool  valid[4];
    const float4* srow[4];
    const float4* prow[4];
    #pragma unroll
    for (int i = 0; i < 4; i++) {
        int r = base + rs + 64 * i;
        valid[i] = (r < N_NODES);
        rows[i]  = valid[i] ? r : (N_NODES - 1);   // clamp for safe loads
        srow[i] = reinterpret_cast<const float4*>(side  + (size_t)rows[i] * D);
        prow[i] = reinterpret_cast<const float4*>(prevc + (size_t)rows[i] * OD);
    }

    float acc[4][16];
    #pragma unroll
    for (int i = 0; i < 4; i++)
        #pragma unroll
        for (int c = 0; c < 16; c++) acc[i][c] = sb[cg * 16 + c];

    #pragma unroll
    for (int j4 = 0; j4 < 16; j4++) {
        float4 s4[4], p4[4];
        #pragma unroll
        for (int i = 0; i < 4; i++) { s4[i] = srow[i][j4]; p4[i] = prow[i][j4]; }
        #pragma unroll
        for (int jj = 0; jj < 4; jj++) {
            int j = j4 * 4 + jj;
            const float4* wsr = reinterpret_cast<const float4*>(sWs + j * D + cg * 16);
            const float4* wpr = reinterpret_cast<const float4*>(sWp + j * D + cg * 16);
            #pragma unroll
            for (int q = 0; q < 4; q++) {
                float4 w1 = wsr[q], w2 = wpr[q];
                #pragma unroll
                for (int i = 0; i < 4; i++) {
                    float s  = (jj == 0) ? s4[i].x : (jj == 1) ? s4[i].y
                             : (jj == 2) ? s4[i].z : s4[i].w;
                    float pv = (jj == 0) ? p4[i].x : (jj == 1) ? p4[i].y
                             : (jj == 2) ? p4[i].z : p4[i].w;
                    float sp = s * pv;
                    acc[i][q*4+0] += s * w1.x + sp * w2.x;
                    acc[i][q*4+1] += s * w1.y + sp * w2.y;
                    acc[i][q*4+2] += s * w1.z + sp * w2.z;
                    acc[i][q*4+3] += s * w1.w + sp * w2.w;
                }
            }
        }
    }

    // leaky relu + rowwise L2 norm (4 threads share a row) + store
    #pragma unroll
    for (int i = 0; i < 4; i++) {
        float sq = 0.0f;
        #pragma unroll
        for (int c = 0; c < 16; c++) {
            float v = acc[i][c];
            v = (v >= 0.0f) ? v : 0.2f * v;
            acc[i][c] = v;
            sq += v * v;
        }
        sq += __shfl_xor_sync(0xffffffffu, sq, 1);
        sq += __shfl_xor_sync(0xffffffffu, sq, 2);
        float inv = 1.0f / fmaxf(sqrtf(sq), 1e-12f);
        if (valid[i]) {
            float* dst = outc + (size_t)rows[i] * OD + cg * 16;
            #pragma unroll
            for (int q = 0; q < 4; q++) {
                float4 o;
                o.x = acc[i][q*4+0] * inv; o.y = acc[i][q*4+1] * inv;
                o.z = acc[i][q*4+2] * inv; o.w = acc[i][q*4+3] * inv;
                reinterpret_cast<float4*>(dst)[q] = o;
            }
        }
    }
}

// ---------------- launch ----------------
extern "C" void kernel_launch(void* const* d_in, const int* in_sizes, int n_in,
                              void* d_out, int out_size) {
    (void)in_sizes; (void)n_in; (void)out_size;
    const int*   cols = (const int*)d_in[1];
    const float* vals = (const float*)d_in[2];
    const float* ue   = (const float*)d_in[3];
    const float* ie   = (const float*)d_in[4];
    float* out = (float*)d_out;

    // ego embeddings -> out columns [0,64)
    {
        int tot = N_NODES * (D / 4);
        ego_copy_kernel<<<(tot + 255) / 256, 256>>>(ue, ie, out);
    }

    // build item CSR (per-launch, deterministic work)
    zero_counts_kernel<<<(N_ITEMS + 255) / 256, 256>>>();
    hist_kernel<<<(E_UI + 255) / 256, 256>>>(cols);
    offsets_kernel<<<(N_ITEMS + 255) / 256, 256>>>();
    fill_kernel<<<(E_UI + 255) / 256, 256>>>(cols);

    // 3 NGCF layers, each writing out columns [64(k+1), 64(k+2))
    for (int k = 0; k < 3; k++) {
        const float* prevc = out + (size_t)64 * k;        // stride OD
        float*       outc  = out + (size_t)64 * (k + 1);  // stride OD
        const float* Ws = (const float*)d_in[5 + 4 * k + 0];
        const float* bs = (const float*)d_in[5 + 4 * k + 1];
        const float* Wp = (const float*)d_in[5 + 4 * k + 2];
        const float* bp = (const float*)d_in[5 + 4 * k + 3];

        spmm_all_kernel<<<(N_NODES * 16 + 255) / 256, 256>>>(cols, vals, prevc, g_side);
        dense_layer_kernel<<<(N_NODES + 255) / 256, 256>>>(g_side, prevc, outc, Ws, bs, Wp, bp);
    }
}